// round 8
// baseline (speedup 1.0000x reference)
#include <cuda_runtime.h>

#define SEQ_LEN   8192
#define HIDDEN    1024
#define H4        256                 // float4 per row
#define NUM_SPANS 4096
#define MAX_W     32
#define SPB       8                   // sorted spans per block
#define SCORE_BLOCKS 1024             // blocks 0..1023 score, block 1024 sorts

__device__ float g_scores[SEQ_LEN];
__device__ int   g_sorted[NUM_SPANS];

// packed f32x2 fma: d = a*b + d  (2 floats per instruction)
__device__ __forceinline__ void ffma2(unsigned long long& d,
                                      unsigned long long a,
                                      unsigned long long b) {
    asm("fma.rn.f32x2 %0, %1, %2, %0;" : "+l"(d) : "l"(a), "l"(b));
}

// ---------------- Kernel 1: scores (blocks 0..1023) + full sort (block 1024)
__global__ __launch_bounds__(256) void setup_kernel(
        const float* __restrict__ emb,
        const float* __restrict__ attn_w,
        const float* __restrict__ attn_b,
        const int*   __restrict__ starts) {
    __shared__ int s_cnt[SEQ_LEN];        // 32 KB: sort histogram/offsets
    __shared__ int s_wtot[8];

    if (blockIdx.x < SCORE_BLOCKS) {
        // ---- per-position logits: one warp per row ----
        int warp = (blockIdx.x * 256 + threadIdx.x) >> 5;
        int lane = threadIdx.x & 31;

        const float4* row = (const float4*)(emb) + (size_t)warp * H4;
        const float4* wv  = (const float4*)(attn_w);

        float acc = 0.0f;
#pragma unroll
        for (int j = 0; j < H4 / 32; j++) {
            float4 a = row[j * 32 + lane];
            float4 c = wv [j * 32 + lane];
            acc += a.x * c.x + a.y * c.y + a.z * c.z + a.w * c.w;
        }
#pragma unroll
        for (int off = 16; off; off >>= 1)
            acc += __shfl_xor_sync(0xffffffffu, acc, off);

        if (lane == 0) g_scores[warp] = acc + attn_b[0];
        return;
    }

    // ---- block 1024: counting sort of spans by start, entirely in smem ----
    const int t = threadIdx.x;            // 256 threads
    for (int i = t; i < SEQ_LEN; i += 256) s_cnt[i] = 0;
    __syncthreads();

    for (int j = t; j < NUM_SPANS; j += 256)
        atomicAdd(&s_cnt[starts[j]], 1);
    __syncthreads();

    // exclusive scan of 8192 counters: 32 per thread
    const int base = t * 32;
    int tsum = 0;
    for (int i = 0; i < 32; i++) tsum += s_cnt[base + i];

    const int lane = t & 31, wid = t >> 5;
    int x = tsum;
#pragma unroll
    for (int off = 1; off < 32; off <<= 1) {
        int y = __shfl_up_sync(0xffffffffu, x, off);
        if (lane >= off) x += y;
    }
    if (lane == 31) s_wtot[wid] = x;
    __syncthreads();
    int woff = 0;
    for (int w = 0; w < wid; w++) woff += s_wtot[w];
    int excl = woff + x - tsum;           // exclusive prefix of this thread

    for (int i = 0; i < 32; i++) {
        int c = s_cnt[base + i];
        s_cnt[base + i] = excl;
        excl += c;
    }
    __syncthreads();

    for (int j = t; j < NUM_SPANS; j += 256) {
        int p = atomicAdd(&s_cnt[starts[j]], 1);
        g_sorted[p] = j;
    }
}

// ---------------- Kernel 2: main — 8 sorted spans/block, row-major --------
__global__ __launch_bounds__(256) void span_main(
        const float* __restrict__ emb,
        const int*   __restrict__ starts,
        const int*   __restrict__ ends,
        float*       __restrict__ out) {
    __shared__ unsigned long long s_wp[SPB][MAX_W];   // packed {w,w}
    __shared__ int s_s[SPB], s_wd[SPB], s_j[SPB];

    const int tid  = threadIdx.x;         // 256 == H4: one float4 column
    const int wid  = tid >> 5;
    const int lane = tid & 31;

    // ---- warp w: softmax for slot w; store packed weights ----
    {
        int j = g_sorted[blockIdx.x * SPB + wid];
        int s = starts[j];
        int W = ends[j] - s;              // width-1 in [0,31]
        float sc = (lane <= W) ? g_scores[s + lane] : -1e9f;
        float m = sc;
#pragma unroll
        for (int off = 16; off; off >>= 1)
            m = fmaxf(m, __shfl_xor_sync(0xffffffffu, m, off));
        float p = __expf(sc - m);
        float sum = p;
#pragma unroll
        for (int off = 16; off; off >>= 1)
            sum += __shfl_xor_sync(0xffffffffu, sum, off);
        float wgt = p / sum;
        unsigned long long w2;
        asm("mov.b64 %0, {%1, %1};" : "=l"(w2) : "f"(wgt));
        s_wp[wid][lane] = w2;
        if (lane == 0) { s_s[wid] = s; s_wd[wid] = W; s_j[wid] = j; }
    }
    __syncthreads();

    int ss[SPB], wd[SPB], obase[SPB];
#pragma unroll
    for (int k = 0; k < SPB; k++) {
        ss[k] = s_s[k];
        wd[k] = s_wd[k];
        obase[k] = s_j[k] * (3 * H4);
    }

    int rmin = ss[0];                      // sorted by start
    int rmax = ss[0] + wd[0];
#pragma unroll
    for (int k = 1; k < SPB; k++) rmax = max(rmax, ss[k] + wd[k]);

    unsigned long long axy[SPB], azw[SPB];
#pragma unroll
    for (int k = 0; k < SPB; k++) { axy[k] = 0ull; azw[k] = 0ull; }

    const float4* col = (const float4*)(emb) + tid;
    float4*       ob  = (float4*)(out) + tid;

    // ---- single pass over the union row window ----
    for (int r = rmin; r <= rmax; r++) {
        float4 v = col[(size_t)r * H4];    // one load, used by up to 8 spans
        unsigned long long vxy, vzw;
        asm("mov.b64 %0, {%1, %2};" : "=l"(vxy) : "f"(v.x), "f"(v.y));
        asm("mov.b64 %0, {%1, %2};" : "=l"(vzw) : "f"(v.z), "f"(v.w));
#pragma unroll
        for (int k = 0; k < SPB; k++) {
            int rel = r - ss[k];
            if ((unsigned)rel <= (unsigned)wd[k]) {
                unsigned long long w2 = s_wp[k][rel];
                ffma2(axy[k], w2, vxy);
                ffma2(azw[k], w2, vzw);
                if (rel == 0)     ob[obase[k]]      = v;   // start_emb
                if (rel == wd[k]) ob[obase[k] + H4] = v;   // end_emb
            }
        }
    }
#pragma unroll
    for (int k = 0; k < SPB; k++) {
        float4 o;
        asm("mov.b64 {%0, %1}, %2;" : "=f"(o.x), "=f"(o.y) : "l"(axy[k]));
        asm("mov.b64 {%0, %1}, %2;" : "=f"(o.z), "=f"(o.w) : "l"(azw[k]));
        ob[obase[k] + 2 * H4] = o;                         // attn_out
    }
}

extern "C" void kernel_launch(void* const* d_in, const int* in_sizes, int n_in,
                              void* d_out, int out_size) {
    const float* emb    = (const float*)d_in[0];
    const int*   starts = (const int*)  d_in[1];
    const int*   ends   = (const int*)  d_in[2];
    const float* attn_w = (const float*)d_in[3];
    const float* attn_b = (const float*)d_in[4];
    float*       out    = (float*)d_out;

    setup_kernel<<<SCORE_BLOCKS + 1, 256>>>(emb, attn_w, attn_b, starts);
    span_main<<<NUM_SPANS / SPB, 256>>>(emb, starts, ends, out);
}

// round 9
// speedup vs baseline: 1.2861x; 1.2861x over previous
#include <cuda_runtime.h>

#define SEQ_LEN   8192
#define HIDDEN    1024
#define H4        256                 // float4 per row
#define NUM_SPANS 4096
#define MAX_W     32
#define SPB       8                   // sorted spans per block
#define WCAP      64                  // max union-window rows for fast path
#define SCORE_BLOCKS 1024             // blocks 0..1023 score, block 1024 sorts

__device__ float g_scores[SEQ_LEN];
__device__ int   g_sorted[NUM_SPANS];

typedef unsigned long long ull;

// packed f32x2 fma: d = a*b + d
__device__ __forceinline__ void ffma2(ull& d, ull a, ull b) {
    asm("fma.rn.f32x2 %0, %1, %2, %0;" : "+l"(d) : "l"(a), "l"(b));
}
__device__ __forceinline__ ull packf2(float lo, float hi) {
    ull r; asm("mov.b64 %0, {%1, %2};" : "=l"(r) : "f"(lo), "f"(hi)); return r;
}
__device__ __forceinline__ float2 unpackf2(ull v) {
    float2 r; asm("mov.b64 {%0, %1}, %2;" : "=f"(r.x), "=f"(r.y) : "l"(v)); return r;
}

// ---------------- Kernel 1: scores (blocks 0..1023) + full sort (block 1024)
__global__ __launch_bounds__(256) void setup_kernel(
        const float* __restrict__ emb,
        const float* __restrict__ attn_w,
        const float* __restrict__ attn_b,
        const int*   __restrict__ starts) {
    __shared__ int s_cnt[SEQ_LEN];        // 32 KB: sort histogram/offsets
    __shared__ int s_wtot[8];

    if (blockIdx.x < SCORE_BLOCKS) {
        int warp = (blockIdx.x * 256 + threadIdx.x) >> 5;
        int lane = threadIdx.x & 31;

        const float4* row = (const float4*)(emb) + (size_t)warp * H4;
        const float4* wv  = (const float4*)(attn_w);

        float acc = 0.0f;
#pragma unroll
        for (int j = 0; j < H4 / 32; j++) {
            float4 a = row[j * 32 + lane];
            float4 c = wv [j * 32 + lane];
            acc += a.x * c.x + a.y * c.y + a.z * c.z + a.w * c.w;
        }
#pragma unroll
        for (int off = 16; off; off >>= 1)
            acc += __shfl_xor_sync(0xffffffffu, acc, off);

        if (lane == 0) g_scores[warp] = acc + attn_b[0];
        return;
    }

    // ---- block 1024: counting sort of spans by start, entirely in smem ----
    const int t = threadIdx.x;
    for (int i = t; i < SEQ_LEN; i += 256) s_cnt[i] = 0;
    __syncthreads();

    for (int j = t; j < NUM_SPANS; j += 256)
        atomicAdd(&s_cnt[starts[j]], 1);
    __syncthreads();

    const int base = t * 32;
    int tsum = 0;
    for (int i = 0; i < 32; i++) tsum += s_cnt[base + i];

    const int lane = t & 31, wid = t >> 5;
    int x = tsum;
#pragma unroll
    for (int off = 1; off < 32; off <<= 1) {
        int y = __shfl_up_sync(0xffffffffu, x, off);
        if (lane >= off) x += y;
    }
    if (lane == 31) s_wtot[wid] = x;
    __syncthreads();
    int woff = 0;
    for (int w = 0; w < wid; w++) woff += s_wtot[w];
    int excl = woff + x - tsum;

    for (int i = 0; i < 32; i++) {
        int c = s_cnt[base + i];
        s_cnt[base + i] = excl;
        excl += c;
    }
    __syncthreads();

    for (int j = t; j < NUM_SPANS; j += 256) {
        int p = atomicAdd(&s_cnt[starts[j]], 1);
        g_sorted[p] = j;
    }
}

// ---------------- Kernel 2: main — branchless zero-padded weight table ----
__global__ __launch_bounds__(256) void span_main(
        const float* __restrict__ emb,
        const int*   __restrict__ starts,
        const int*   __restrict__ ends,
        float*       __restrict__ out) {
    __shared__ ulonglong2 s_wt[WCAP][SPB / 2];        // zero-padded, 4 KB
    __shared__ ull s_wp[SPB][MAX_W];                  // per-span packed weights
    __shared__ int s_s[SPB], s_wd[SPB], s_j[SPB];

    const int tid  = threadIdx.x;         // 256 == H4: one float4 column
    const int wid  = tid >> 5;
    const int lane = tid & 31;

    // ---- warp w: softmax for slot w ----
    {
        int j = g_sorted[blockIdx.x * SPB + wid];
        int s = starts[j];
        int W = ends[j] - s;              // width-1 in [0,31]
        float sc = (lane <= W) ? g_scores[s + lane] : -1e9f;
        float m = sc;
#pragma unroll
        for (int off = 16; off; off >>= 1)
            m = fmaxf(m, __shfl_xor_sync(0xffffffffu, m, off));
        float p = __expf(sc - m);
        float sum = p;
#pragma unroll
        for (int off = 16; off; off >>= 1)
            sum += __shfl_xor_sync(0xffffffffu, sum, off);
        float wgt = p / sum;
        s_wp[wid][lane] = packf2(wgt, wgt);
        if (lane == 0) { s_s[wid] = s; s_wd[wid] = W; s_j[wid] = j; }
    }
    // zero the weight table while softmax results settle
    ((ulonglong2*)s_wt)[tid] = make_ulonglong2(0ull, 0ull);   // 256 entries
    __syncthreads();

    int ss[SPB], wd[SPB];
#pragma unroll
    for (int k = 0; k < SPB; k++) { ss[k] = s_s[k]; wd[k] = s_wd[k]; }

    const int rmin = ss[0];               // sorted by start
    int rmax = ss[0] + wd[0];
#pragma unroll
    for (int k = 1; k < SPB; k++) rmax = max(rmax, ss[k] + wd[k]);
    const int win = rmax - rmin + 1;

    const float4* eb = (const float4*)(emb);
    float4*       ob = (float4*)(out);

    if (win <= WCAP) {
        // ---- scatter this warp's weights into the zero-padded table ----
        if (lane <= s_wd[wid])
            ((ull*)s_wt)[(s_s[wid] - rmin + lane) * SPB + wid] = s_wp[wid][lane];
        __syncthreads();

        ull axy[SPB], azw[SPB];
#pragma unroll
        for (int k = 0; k < SPB; k++) { axy[k] = 0ull; azw[k] = 0ull; }

        const float4* p = eb + (size_t)rmin * H4 + tid;

        // ---- branchless hot loop ----
        for (int rw = 0; rw < win; rw++, p += H4) {
            float4 v = *p;
            ull vxy = packf2(v.x, v.y);
            ull vzw = packf2(v.z, v.w);
            ulonglong2 w01 = s_wt[rw][0];
            ulonglong2 w23 = s_wt[rw][1];
            ulonglong2 w45 = s_wt[rw][2];
            ulonglong2 w67 = s_wt[rw][3];
            ffma2(axy[0], w01.x, vxy); ffma2(azw[0], w01.x, vzw);
            ffma2(axy[1], w01.y, vxy); ffma2(azw[1], w01.y, vzw);
            ffma2(axy[2], w23.x, vxy); ffma2(azw[2], w23.x, vzw);
            ffma2(axy[3], w23.y, vxy); ffma2(azw[3], w23.y, vzw);
            ffma2(axy[4], w45.x, vxy); ffma2(azw[4], w45.x, vzw);
            ffma2(axy[5], w45.y, vxy); ffma2(azw[5], w45.y, vzw);
            ffma2(axy[6], w67.x, vxy); ffma2(azw[6], w67.x, vzw);
            ffma2(axy[7], w67.y, vxy); ffma2(azw[7], w67.y, vzw);
        }

        // ---- epilogue: attn_out + start/end copies (window rows are hot) ----
#pragma unroll
        for (int k = 0; k < SPB; k++) {
            int obase = s_j[k] * (3 * H4);
            float2 xy = unpackf2(axy[k]);
            float2 zw = unpackf2(azw[k]);
            ob[obase + 2 * H4 + tid] = make_float4(xy.x, xy.y, zw.x, zw.y);
            float4 sv = eb[(size_t)ss[k] * H4 + tid];
            float4 ev = eb[(size_t)(ss[k] + wd[k]) * H4 + tid];
            ob[obase + tid]      = sv;
            ob[obase + H4 + tid] = ev;
        }
    } else {
        // ---- rare slow path: warp-per-span, lane covers 8 float4 columns ----
        const int s = ss[wid], W = wd[wid];
        const float4* bp = eb + (size_t)s * H4 + lane;
        float4*       o  = ob + (size_t)s_j[wid] * (3 * H4) + lane;

        float4 acc[8];
#pragma unroll
        for (int c = 0; c < 8; c++) acc[c] = make_float4(0.f, 0.f, 0.f, 0.f);

        for (int r = 0; r <= W; r++) {
            float wgt = ((const float*)&s_wp[wid][r])[0];
            const float4* rp = bp + (size_t)r * H4;
            const bool first = (r == 0), last = (r == W);
#pragma unroll
            for (int c = 0; c < 8; c++) {
                float4 v = rp[c * 32];
                acc[c].x = fmaf(wgt, v.x, acc[c].x);
                acc[c].y = fmaf(wgt, v.y, acc[c].y);
                acc[c].z = fmaf(wgt, v.z, acc[c].z);
                acc[c].w = fmaf(wgt, v.w, acc[c].w);
                if (first) o[c * 32]      = v;
                if (last)  o[H4 + c * 32] = v;
            }
        }
#pragma unroll
        for (int c = 0; c < 8; c++) o[2 * H4 + c * 32] = acc[c];
    }
}

extern "C" void kernel_launch(void* const* d_in, const int* in_sizes, int n_in,
                              void* d_out, int out_size) {
    const float* emb    = (const float*)d_in[0];
    const int*   starts = (const int*)  d_in[1];
    const int*   ends   = (const int*)  d_in[2];
    const float* attn_w = (const float*)d_in[3];
    const float* attn_b = (const float*)d_in[4];
    float*       out    = (float*)d_out;

    setup_kernel<<<SCORE_BLOCKS + 1, 256>>>(emb, attn_w, attn_b, starts);
    span_main<<<NUM_SPANS / SPB, 256>>>(emb, starts, ends, out);
}

// round 10
// speedup vs baseline: 1.8780x; 1.4602x over previous
#include <cuda_runtime.h>

#define SEQ_LEN   8192
#define HIDDEN    1024
#define H4        256                 // float4 per row
#define NUM_SPANS 4096
#define MAX_W     32
#define SPB       8                   // sorted spans per block
#define WCAP      64                  // max union-window rows for fast path
#define SCORE_BLOCKS 256              // 1024-thr blocks: 32 rows each

__device__ float g_scores[SEQ_LEN];
__device__ int   g_sorted[NUM_SPANS];

typedef unsigned long long ull;

// packed f32x2 fma: d = a*b + d
__device__ __forceinline__ void ffma2(ull& d, ull a, ull b) {
    asm("fma.rn.f32x2 %0, %1, %2, %0;" : "+l"(d) : "l"(a), "l"(b));
}
__device__ __forceinline__ ull packf2(float lo, float hi) {
    ull r; asm("mov.b64 %0, {%1, %2};" : "=l"(r) : "f"(lo), "f"(hi)); return r;
}
__device__ __forceinline__ float2 unpackf2(ull v) {
    float2 r; asm("mov.b64 {%0, %1}, %2;" : "=f"(r.x), "=f"(r.y) : "l"(v)); return r;
}

// ---------------- Kernel 1: scores (blocks 0..255) + full sort (block 256) -
__global__ __launch_bounds__(1024) void setup_kernel(
        const float* __restrict__ emb,
        const float* __restrict__ attn_w,
        const float* __restrict__ attn_b,
        const int*   __restrict__ starts) {
    __shared__ int s_cnt[SEQ_LEN];        // 32 KB: sort histogram/offsets
    __shared__ int s_wtot[32];

    if (blockIdx.x < SCORE_BLOCKS) {
        // ---- per-position logits: one warp per row, 32 rows/block ----
        int warp = (blockIdx.x * 1024 + threadIdx.x) >> 5;
        int lane = threadIdx.x & 31;

        const float4* row = (const float4*)(emb) + (size_t)warp * H4;
        const float4* wv  = (const float4*)(attn_w);

        float acc = 0.0f;
#pragma unroll
        for (int j = 0; j < H4 / 32; j++) {
            float4 a = row[j * 32 + lane];
            float4 c = wv [j * 32 + lane];
            acc += a.x * c.x + a.y * c.y + a.z * c.z + a.w * c.w;
        }
#pragma unroll
        for (int off = 16; off; off >>= 1)
            acc += __shfl_xor_sync(0xffffffffu, acc, off);

        if (lane == 0) g_scores[warp] = acc + attn_b[0];
        return;
    }

    // ---- block 256: counting sort of spans by start, entirely in smem ----
    const int t = threadIdx.x;            // 1024 threads
    for (int i = t; i < SEQ_LEN; i += 1024) s_cnt[i] = 0;
    __syncthreads();

    for (int j = t; j < NUM_SPANS; j += 1024)
        atomicAdd(&s_cnt[starts[j]], 1);
    __syncthreads();

    // exclusive scan of 8192 counters: 8 per thread
    const int base = t * 8;
    int loc[8];
    int tsum = 0;
#pragma unroll
    for (int i = 0; i < 8; i++) { loc[i] = tsum; tsum += s_cnt[base + i]; }

    const int lane = t & 31, wid = t >> 5;
    int x = tsum;
#pragma unroll
    for (int off = 1; off < 32; off <<= 1) {
        int y = __shfl_up_sync(0xffffffffu, x, off);
        if (lane >= off) x += y;
    }
    if (lane == 31) s_wtot[wid] = x;
    __syncthreads();
    if (wid == 0) {
        int s = s_wtot[lane];
#pragma unroll
        for (int off = 1; off < 32; off <<= 1) {
            int y = __shfl_up_sync(0xffffffffu, s, off);
            if (lane >= off) s += y;
        }
        s_wtot[lane] = s;
    }
    __syncthreads();

    int excl = x - tsum + (wid ? s_wtot[wid - 1] : 0);
#pragma unroll
    for (int i = 0; i < 8; i++) s_cnt[base + i] = excl + loc[i];
    __syncthreads();

    for (int j = t; j < NUM_SPANS; j += 1024) {
        int p = atomicAdd(&s_cnt[starts[j]], 1);
        g_sorted[p] = j;
    }
}

// ---------------- Kernel 2: main — branchless + prefetch pipeline ---------
__global__ __launch_bounds__(256) void span_main(
        const float* __restrict__ emb,
        const int*   __restrict__ starts,
        const int*   __restrict__ ends,
        float*       __restrict__ out) {
    __shared__ ulonglong2 s_wt[WCAP][SPB / 2];        // zero-padded, 4 KB
    __shared__ ull s_wp[SPB][MAX_W];                  // per-span packed weights
    __shared__ int s_s[SPB], s_wd[SPB], s_j[SPB];

    const int tid  = threadIdx.x;         // 256 == H4: one float4 column
    const int wid  = tid >> 5;
    const int lane = tid & 31;

    // ---- warp w: softmax for slot w ----
    {
        int j = g_sorted[blockIdx.x * SPB + wid];
        int s = starts[j];
        int W = ends[j] - s;              // width-1 in [0,31]
        float sc = (lane <= W) ? g_scores[s + lane] : -1e9f;
        float m = sc;
#pragma unroll
        for (int off = 16; off; off >>= 1)
            m = fmaxf(m, __shfl_xor_sync(0xffffffffu, m, off));
        float p = __expf(sc - m);
        float sum = p;
#pragma unroll
        for (int off = 16; off; off >>= 1)
            sum += __shfl_xor_sync(0xffffffffu, sum, off);
        float wgt = p / sum;
        s_wp[wid][lane] = packf2(wgt, wgt);
        if (lane == 0) { s_s[wid] = s; s_wd[wid] = W; s_j[wid] = j; }
    }
    // zero the weight table while softmax results settle
    ((ulonglong2*)s_wt)[tid] = make_ulonglong2(0ull, 0ull);   // 256 entries
    __syncthreads();

    int ss[SPB], wd[SPB];
#pragma unroll
    for (int k = 0; k < SPB; k++) { ss[k] = s_s[k]; wd[k] = s_wd[k]; }

    const int rmin = ss[0];               // sorted by start
    int rmax = ss[0] + wd[0];
#pragma unroll
    for (int k = 1; k < SPB; k++) rmax = max(rmax, ss[k] + wd[k]);
    const int win = rmax - rmin + 1;

    const float4* eb = (const float4*)(emb);
    float4*       ob = (float4*)(out);

    if (win <= WCAP) {
        // ---- scatter this warp's weights into the zero-padded table ----
        if (lane <= s_wd[wid])
            ((ull*)s_wt)[(s_s[wid] - rmin + lane) * SPB + wid] = s_wp[wid][lane];
        __syncthreads();

        ull axy[SPB], azw[SPB];
#pragma unroll
        for (int k = 0; k < SPB; k++) { axy[k] = 0ull; azw[k] = 0ull; }

        // emb row as ulonglong2: .x = packed{x,y}, .y = packed{z,w}
        const ulonglong2* p = (const ulonglong2*)(eb + (size_t)rmin * H4 + tid);

        // prefetch row 0; pipeline depth 1 (rmax+1 <= 8191, always in bounds)
        ulonglong2 v = *p;
        p += H4;

        for (int rw = 0; rw < win; rw++) {
            ulonglong2 vn = *p;            // next row (L2), consumed next iter
            p += H4;
            ulonglong2 w01 = s_wt[rw][0];
            ulonglong2 w23 = s_wt[rw][1];
            ulonglong2 w45 = s_wt[rw][2];
            ulonglong2 w67 = s_wt[rw][3];
            ffma2(axy[0], w01.x, v.x); ffma2(azw[0], w01.x, v.y);
            ffma2(axy[1], w01.y, v.x); ffma2(azw[1], w01.y, v.y);
            ffma2(axy[2], w23.x, v.x); ffma2(azw[2], w23.x, v.y);
            ffma2(axy[3], w23.y, v.x); ffma2(azw[3], w23.y, v.y);
            ffma2(axy[4], w45.x, v.x); ffma2(azw[4], w45.x, v.y);
            ffma2(axy[5], w45.y, v.x); ffma2(azw[5], w45.y, v.y);
            ffma2(axy[6], w67.x, v.x); ffma2(azw[6], w67.x, v.y);
            ffma2(axy[7], w67.y, v.x); ffma2(azw[7], w67.y, v.y);
            v = vn;
        }

        // ---- epilogue: attn_out + start/end copies (window rows are hot) ----
#pragma unroll
        for (int k = 0; k < SPB; k++) {
            int obase = s_j[k] * (3 * H4);
            float2 xy = unpackf2(axy[k]);
            float2 zw = unpackf2(azw[k]);
            ob[obase + 2 * H4 + tid] = make_float4(xy.x, xy.y, zw.x, zw.y);
            float4 sv = eb[(size_t)ss[k] * H4 + tid];
            float4 ev = eb[(size_t)(ss[k] + wd[k]) * H4 + tid];
            ob[obase + tid]      = sv;
            ob[obase + H4 + tid] = ev;
        }
    } else {
        // ---- rare slow path: warp-per-span, lane covers 8 float4 columns ----
        const int s = ss[wid], W = wd[wid];
        const float4* bp = eb + (size_t)s * H4 + lane;
        float4*       o  = ob + (size_t)s_j[wid] * (3 * H4) + lane;

        float4 acc[8];
#pragma unroll
        for (int c = 0; c < 8; c++) acc[c] = make_float4(0.f, 0.f, 0.f, 0.f);

        for (int r = 0; r <= W; r++) {
            float wgt = ((const float*)&s_wp[wid][r])[0];
            const float4* rp = bp + (size_t)r * H4;
            const bool first = (r == 0), last = (r == W);
#pragma unroll
            for (int c = 0; c < 8; c++) {
                float4 v = rp[c * 32];
                acc[c].x = fmaf(wgt, v.x, acc[c].x);
                acc[c].y = fmaf(wgt, v.y, acc[c].y);
                acc[c].z = fmaf(wgt, v.z, acc[c].z);
                acc[c].w = fmaf(wgt, v.w, acc[c].w);
                if (first) o[c * 32]      = v;
                if (last)  o[H4 + c * 32] = v;
            }
        }
#pragma unroll
        for (int c = 0; c < 8; c++) o[2 * H4 + c * 32] = acc[c];
    }
}

extern "C" void kernel_launch(void* const* d_in, const int* in_sizes, int n_in,
                              void* d_out, int out_size) {
    const float* emb    = (const float*)d_in[0];
    const int*   starts = (const int*)  d_in[1];
    const int*   ends   = (const int*)  d_in[2];
    const float* attn_w = (const float*)d_in[3];
    const float* attn_b = (const float*)d_in[4];
    float*       out    = (float*)d_out;

    setup_kernel<<<SCORE_BLOCKS + 1, 1024>>>(emb, attn_w, attn_b, starts);
    span_main<<<NUM_SPANS / SPB, 256>>>(emb, starts, ends, out);
}